// round 8
// baseline (speedup 1.0000x reference)
#include <cuda_runtime.h>
#include <cstdint>

#define B 16
#define H0 720
#define W0 720
#define HP 359
#define WP 359
#define H2 357
#define W2 357
#define H3 355
#define W3 355

#define W1P 368
#define W2P 368

// A-tile plane stride in float2 units (conflict-free: *2 mod 32 == 8)
#define PL 1412

__device__ __align__(128) float g_p1[B * 10 * HP * W1P];
__device__ __align__(128) float g_p2[B * 16 * H2 * W2P];

// packed B-fragment images: [s][g][t] with nt pairs; float2 elements
__device__ __align__(16) float2 g_w2B[18 * 64];    // conv2: nt 0..1
__device__ __align__(16) float2 g_w3B[18 * 128];   // conv3: nt 0..3 (hi half at +64)

typedef unsigned long long ull;

__device__ __forceinline__ ull pack2(float a, float b) {
    ull r;
    asm("mov.b64 %0, {%1,%2};" : "=l"(r) : "f"(a), "f"(b));
    return r;
}
__device__ __forceinline__ void fma2(ull& d, ull a, ull b) {
    asm("fma.rn.f32x2 %0, %1, %2, %0;" : "+l"(d) : "l"(a), "l"(b));
}
__device__ __forceinline__ float2 unpack2(ull v) {
    float2 f;
    asm("mov.b64 {%0,%1}, %2;" : "=f"(f.x), "=f"(f.y) : "l"(v));
    return f;
}
__device__ __forceinline__ float to_tf32(float f) {
    uint32_t u;
    asm("cvt.rna.tf32.f32 %0, %1;" : "=r"(u) : "f"(f));
    return __uint_as_float(u);
}
__device__ __forceinline__ void mma_tf32(float d[4],
                                         float a0, float a1, float a2, float a3,
                                         float b0, float b1) {
    asm("mma.sync.aligned.m16n8k8.row.col.f32.tf32.tf32.f32 "
        "{%0,%1,%2,%3}, {%4,%5,%6,%7}, {%8,%9}, {%0,%1,%2,%3};"
        : "+f"(d[0]), "+f"(d[1]), "+f"(d[2]), "+f"(d[3])
        : "r"(__float_as_uint(a0)), "r"(__float_as_uint(a1)),
          "r"(__float_as_uint(a2)), "r"(__float_as_uint(a3)),
          "r"(__float_as_uint(b0)), "r"(__float_as_uint(b1)));
}

// =====================================================================
// Prep: pack conv2/conv3 weights into packed fragment images
// =====================================================================
__global__ void k_prep(const float* __restrict__ w2, const float* __restrict__ w3)
{
    int e = blockIdx.x * blockDim.x + threadIdx.x;
    // conv2: 18*4*8*2 = 1152 entries; idx = s*64 + g*8 + t*2 + nt
    if (e < 1152) {
        int nt = e & 1, t = (e >> 1) & 3, g = (e >> 3) & 7, s = e >> 6;
        int h = s & 1, o = s >> 1;
        int ky = o / 3, kx = o - 3 * (o / 3);
        int co = nt * 8 + g;
        int ci0 = h * 8 + t, ci1 = ci0 + 4;
        float f0 = (ci0 < 10) ? w2[((co * 10 + ci0) * 3 + ky) * 3 + kx] : 0.f;
        float f1 = (ci1 < 10) ? w2[((co * 10 + ci1) * 3 + ky) * 3 + kx] : 0.f;
        g_w2B[(s << 6) + (g << 3) + (t << 1) + nt] = make_float2(to_tf32(f0), to_tf32(f1));
    }
    // conv3: 18*4*8*4 = 2304 entries; idx = s*128 + (nt>=2)*64 + g*8 + t*2 + (nt&1)
    if (e < 2304) {
        int nt = e & 3, t = (e >> 2) & 3, g = (e >> 4) & 7, s = e >> 7;
        int h = s & 1, o = s >> 1;
        int ky = o / 3, kx = o - 3 * (o / 3);
        int co = nt * 8 + g;
        int ci0 = h * 8 + t, ci1 = ci0 + 4;
        float f0 = w3[((co * 16 + ci0) * 3 + ky) * 3 + kx];
        float f1 = w3[((co * 16 + ci1) * 3 + ky) * 3 + kx];
        int idx = (s << 7) + ((nt >> 1) << 6) + (g << 3) + (t << 1) + (nt & 1);
        g_w3B[idx] = make_float2(to_tf32(f0), to_tf32(f1));
    }
}

// =====================================================================
// Kernel 1: conv1(3->10,3x3)+PReLU+maxpool, norm folded (unchanged)
// =====================================================================
__global__ __launch_bounds__(64)
void k_conv1_pool(const float* __restrict__ x,
                  const float* __restrict__ w,
                  const float* __restrict__ bias,
                  const float* __restrict__ alpha)
{
    __shared__ ull   s_wd[135];
    __shared__ float s_b2[5];
    __shared__ float s_a2[5];

    int cg = blockIdx.z & 1;
    int b  = blockIdx.z >> 1;

    for (int i = threadIdx.x; i < 135; i += blockDim.x) {
        float wv = w[cg * 135 + i] * 0.0078125f;
        s_wd[i] = pack2(wv, wv);
    }
    if (threadIdx.x < 5) {
        int co = cg * 5 + threadIdx.x;
        float s = 0.f;
#pragma unroll
        for (int k = 0; k < 27; k++) s += w[co * 27 + k];
        s_b2[threadIdx.x] = bias[co] - 127.5f * 0.0078125f * s;
        s_a2[threadIdx.x] = alpha[co];
    }
    __syncthreads();

    int t = blockIdx.x * blockDim.x + threadIdx.x;
    if (t >= 180) return;
    int py = blockIdx.y;
    int iy = 2 * py;
    int x4 = 4 * t;

    ull acc[5][2][2];
#pragma unroll
    for (int co = 0; co < 5; co++) {
        float bb = s_b2[co];
        ull bp = pack2(bb, bb);
        acc[co][0][0] = bp; acc[co][0][1] = bp;
        acc[co][1][0] = bp; acc[co][1][1] = bp;
    }

#pragma unroll
    for (int ci = 0; ci < 3; ci++) {
        const float* rp = x + ((size_t)(b * 3 + ci) * H0 + iy) * W0 + x4;
        ull pr[4][5];
#pragma unroll
        for (int r = 0; r < 4; r++) {
            float4 v4 = *(const float4*)(rp + (size_t)r * W0);
            float2 v2 = make_float2(0.f, 0.f);
            if (t < 179) v2 = *(const float2*)(rp + (size_t)r * W0 + 4);
            pr[r][0] = pack2(v4.x, v4.y);
            pr[r][1] = pack2(v4.y, v4.z);
            pr[r][2] = pack2(v4.z, v4.w);
            pr[r][3] = pack2(v4.w, v2.x);
            pr[r][4] = pack2(v2.x, v2.y);
        }
#pragma unroll
        for (int co = 0; co < 5; co++) {
#pragma unroll
            for (int ky = 0; ky < 3; ky++)
#pragma unroll
                for (int kx = 0; kx < 3; kx++) {
                    ull wd = s_wd[co * 27 + ci * 9 + ky * 3 + kx];
                    fma2(acc[co][0][0], pr[ky    ][kx], wd);
                    fma2(acc[co][0][1], pr[ky    ][kx + 2], wd);
                    fma2(acc[co][1][0], pr[ky + 1][kx], wd);
                    fma2(acc[co][1][1], pr[ky + 1][kx + 2], wd);
                }
        }
    }

#pragma unroll
    for (int co = 0; co < 5; co++) {
        float a = s_a2[co];
        float2 r00 = unpack2(acc[co][0][0]);
        float2 r01 = unpack2(acc[co][0][1]);
        float2 r10 = unpack2(acc[co][1][0]);
        float2 r11 = unpack2(acc[co][1][1]);
        float p00 = r00.x >= 0.f ? r00.x : a * r00.x;
        float p01 = r00.y >= 0.f ? r00.y : a * r00.y;
        float p10 = r10.x >= 0.f ? r10.x : a * r10.x;
        float p11 = r10.y >= 0.f ? r10.y : a * r10.y;
        float q00 = r01.x >= 0.f ? r01.x : a * r01.x;
        float q01 = r01.y >= 0.f ? r01.y : a * r01.y;
        float q10 = r11.x >= 0.f ? r11.x : a * r11.x;
        float q11 = r11.y >= 0.f ? r11.y : a * r11.y;
        float m0 = fmaxf(fmaxf(p00, p01), fmaxf(p10, p11));
        float m1 = fmaxf(fmaxf(q00, q01), fmaxf(q10, q11));
        float* op = g_p1 + ((size_t)(b * 10 + cg * 5 + co) * HP + py) * W1P + 2 * t;
        *(float2*)op = make_float2(to_tf32(m0), to_tf32(m1));
    }
}

// =====================================================================
// Kernel 2: conv2 via tf32 mma, paired-A layout, 256 thr
// =====================================================================
#define SMEM2 (8 * PL * 8 + 1152 * 8 + 128)
__global__ __launch_bounds__(256)
void k_conv2_mma(const float* __restrict__ bias,
                 const float* __restrict__ alpha)
{
    extern __shared__ char smem[];
    float2* s_in   = (float2*)smem;                        // [8][PL]
    float2* s_B    = (float2*)(smem + 8 * PL * 8);         // 1152
    float*  s_bias = (float*)(smem + 8 * PL * 8 + 1152 * 8);
    float*  s_alpha = s_bias + 16;

    int tid = threadIdx.x;
    int b   = blockIdx.z;
    int y0  = blockIdx.y * 8;
    int x0  = blockIdx.x * 128;

    {
        const float4* src = (const float4*)g_w2B;
        float4* dst = (float4*)s_B;
        for (int i = tid; i < 576; i += 256) dst[i] = src[i];
    }
    if (tid < 16) { s_bias[tid] = bias[tid]; s_alpha[tid] = alpha[tid]; }

    // staging: (p, r, xq) -> float2 pairs (ci, ci+4)
    for (int i = tid; i < 8 * 10 * 35; i += 256) {
        int p   = i / 350;
        int rem = i - p * 350;
        int r   = rem / 35;
        int xq  = rem - r * 35;
        int gx  = x0 + xq * 4;
        int grow = y0 + r; if (grow > HP - 1) grow = HP - 1;
        int ci0 = (p >> 2) * 8 + (p & 3);
        int ci1 = ci0 + 4;
        float4 va = make_float4(0.f, 0.f, 0.f, 0.f);
        float4 vb = va;
        if (gx < W1P) {
            if (ci0 < 10) va = *(const float4*)&g_p1[((size_t)(b * 10 + ci0) * HP + grow) * W1P + gx];
            if (ci1 < 10) vb = *(const float4*)&g_p1[((size_t)(b * 10 + ci1) * HP + grow) * W1P + gx];
        }
        float4* dp = (float4*)&s_in[p * PL + r * 140 + xq * 4];
        dp[0] = make_float4(va.x, vb.x, va.y, vb.y);
        dp[1] = make_float4(va.z, vb.z, va.w, vb.w);
    }
    __syncthreads();

    int warp = tid >> 5, lane = tid & 31;
    int warpx = warp & 3, warpr = warp >> 2;
    int g = lane >> 2, t = lane & 3;
    int xw = warpx * 32;
    int rbase = warpr * 4;

    float bval[2][2], aval[2][2];
#pragma unroll
    for (int nt = 0; nt < 2; nt++)
#pragma unroll
        for (int c = 0; c < 2; c++) {
            int co = nt * 8 + 2 * t + c;
            bval[nt][c] = s_bias[co];
            aval[nt][c] = s_alpha[co];
        }

    for (int rr = 0; rr < 4; rr++) {
        int r = rbase + rr;
        int y = y0 + r;
        if (y >= H2) break;
        float D[2][2][4] = {};
#pragma unroll
        for (int s = 0; s < 18; s++) {
            int h = s & 1, o = s >> 1;
            int ky = o / 3, kx = o - 3 * (o / 3);
            float4 b01 = *(const float4*)&s_B[(s << 6) + (g << 3) + (t << 1)];
#pragma unroll
            for (int mt = 0; mt < 2; mt++) {
                const float2* ap = &s_in[(h * 4 + t) * PL + (r + ky) * 140 + xw + mt * 16 + kx + g];
                float2 lo = ap[0];
                float2 hi = ap[8];
                mma_tf32(D[mt][0], lo.x, hi.x, lo.y, hi.y, b01.x, b01.y);
                mma_tf32(D[mt][1], lo.x, hi.x, lo.y, hi.y, b01.z, b01.w);
            }
        }
#pragma unroll
        for (int mt = 0; mt < 2; mt++) {
            int xlo = x0 + xw + mt * 16 + g;
#pragma unroll
            for (int nt = 0; nt < 2; nt++) {
#pragma unroll
                for (int c = 0; c < 2; c++) {
                    int co = nt * 8 + 2 * t + c;
                    float* op = &g_p2[((size_t)(b * 16 + co) * H2 + y) * W2P];
                    float v0 = D[mt][nt][c]     + bval[nt][c];
                    float v1 = D[mt][nt][c + 2] + bval[nt][c];
                    v0 = v0 >= 0.f ? v0 : aval[nt][c] * v0;
                    v1 = v1 >= 0.f ? v1 : aval[nt][c] * v1;
                    if (xlo < W2)     op[xlo]     = to_tf32(v0);
                    if (xlo + 8 < W2) op[xlo + 8] = to_tf32(v1);
                }
            }
        }
    }
}

// =====================================================================
// Kernel 3: conv3+heads via tf32 mma, paired-A layout, 256 thr
// =====================================================================
#define SMEM3 (8 * PL * 8 + 2304 * 8 + 256)
__global__ __launch_bounds__(256)
void k_conv3_heads(const float* __restrict__ bias,
                   const float* __restrict__ alpha,
                   const float* __restrict__ w41,
                   const float* __restrict__ b41,
                   const float* __restrict__ w42,
                   const float* __restrict__ b42,
                   float* __restrict__ out)
{
    extern __shared__ char smem[];
    float2* s_in   = (float2*)smem;                        // [8][PL]
    float2* s_B    = (float2*)(smem + 8 * PL * 8);         // 2304
    float*  s_bias = (float*)(smem + 8 * PL * 8 + 2304 * 8);
    float*  s_alpha = s_bias + 32;

    int tid = threadIdx.x;
    int b   = blockIdx.z;
    int y0  = blockIdx.y * 8;
    int x0  = blockIdx.x * 128;

    {
        const float4* src = (const float4*)g_w3B;
        float4* dst = (float4*)s_B;
        for (int i = tid; i < 1152; i += 256) dst[i] = src[i];
    }
    if (tid < 32) { s_bias[tid] = bias[tid]; s_alpha[tid] = alpha[tid]; }

    for (int i = tid; i < 8 * 10 * 35; i += 256) {
        int p   = i / 350;
        int rem = i - p * 350;
        int r   = rem / 35;
        int xq  = rem - r * 35;
        int gx  = x0 + xq * 4;
        int grow = y0 + r; if (grow > H2 - 1) grow = H2 - 1;
        int ci0 = (p >> 2) * 8 + (p & 3);
        int ci1 = ci0 + 4;
        float4 va = make_float4(0.f, 0.f, 0.f, 0.f);
        float4 vb = va;
        if (gx < W2P) {
            va = *(const float4*)&g_p2[((size_t)(b * 16 + ci0) * H2 + grow) * W2P + gx];
            vb = *(const float4*)&g_p2[((size_t)(b * 16 + ci1) * H2 + grow) * W2P + gx];
        }
        float4* dp = (float4*)&s_in[p * PL + r * 140 + xq * 4];
        dp[0] = make_float4(va.x, vb.x, va.y, vb.y);
        dp[1] = make_float4(va.z, vb.z, va.w, vb.w);
    }
    __syncthreads();

    int warp = tid >> 5, lane = tid & 31;
    int warpx = warp & 3, warpr = warp >> 2;
    int g = lane >> 2, t = lane & 3;
    int xw = warpx * 32;
    int rbase = warpr * 4;

    float bval[4][2], aval[4][2];
    ull whp[4][6];   // packed (c0,c1) head weights per nt
#pragma unroll
    for (int nt = 0; nt < 4; nt++) {
        int co0 = nt * 8 + 2 * t, co1 = co0 + 1;
        bval[nt][0] = s_bias[co0];  bval[nt][1] = s_bias[co1];
        aval[nt][0] = s_alpha[co0]; aval[nt][1] = s_alpha[co1];
        whp[nt][0] = pack2(w41[co0],      w41[co1]);
        whp[nt][1] = pack2(w41[32 + co0], w41[32 + co1]);
        whp[nt][2] = pack2(w42[co0],      w42[co1]);
        whp[nt][3] = pack2(w42[32 + co0], w42[32 + co1]);
        whp[nt][4] = pack2(w42[64 + co0], w42[64 + co1]);
        whp[nt][5] = pack2(w42[96 + co0], w42[96 + co1]);
    }
    float hb0 = b41[0], hb1 = b41[1];
    float hb2 = b42[0], hb3 = b42[1], hb4 = b42[2], hb5 = b42[3];

    const size_t plane = (size_t)H3 * W3;
    const size_t PROB_OFF = (size_t)B * 4 * plane;

    for (int rr = 0; rr < 4; rr++) {
        int r = rbase + rr;
        int y = y0 + r;
        if (y >= H3) break;
        float D[2][4][4] = {};
#pragma unroll
        for (int s = 0; s < 18; s++) {
            int h = s & 1, o = s >> 1;
            int ky = o / 3, kx = o - 3 * (o / 3);
            const float2* bp = &s_B[(s << 7) + (g << 3) + (t << 1)];
            float4 b01 = *(const float4*)bp;
            float4 b23 = *(const float4*)(bp + 64);
#pragma unroll
            for (int mt = 0; mt < 2; mt++) {
                const float2* ap = &s_in[(h * 4 + t) * PL + (r + ky) * 140 + xw + mt * 16 + kx + g];
                float2 lo = ap[0];
                float2 hi = ap[8];
                mma_tf32(D[mt][0], lo.x, hi.x, lo.y, hi.y, b01.x, b01.y);
                mma_tf32(D[mt][1], lo.x, hi.x, lo.y, hi.y, b01.z, b01.w);
                mma_tf32(D[mt][2], lo.x, hi.x, lo.y, hi.y, b23.x, b23.y);
                mma_tf32(D[mt][3], lo.x, hi.x, lo.y, hi.y, b23.z, b23.w);
            }
        }

        size_t rowbase = (size_t)y * W3;
#pragma unroll
        for (int mt = 0; mt < 2; mt++) {
#pragma unroll
            for (int p = 0; p < 2; p++) {
                ull A0 = 0, A1 = 0, A2 = 0, A3 = 0, A4 = 0, A5 = 0;
#pragma unroll
                for (int nt = 0; nt < 4; nt++) {
                    float v0 = D[mt][nt][2 * p]     + bval[nt][0];
                    float v1 = D[mt][nt][2 * p + 1] + bval[nt][1];
                    v0 = v0 >= 0.f ? v0 : aval[nt][0] * v0;
                    v1 = v1 >= 0.f ? v1 : aval[nt][1] * v1;
                    ull vp = pack2(v0, v1);
                    fma2(A0, vp, whp[nt][0]);
                    fma2(A1, vp, whp[nt][1]);
                    fma2(A2, vp, whp[nt][2]);
                    fma2(A3, vp, whp[nt][3]);
                    fma2(A4, vp, whp[nt][4]);
                    fma2(A5, vp, whp[nt][5]);
                }
                float2 f0 = unpack2(A0), f1 = unpack2(A1), f2 = unpack2(A2);
                float2 f3 = unpack2(A3), f4 = unpack2(A4), f5 = unpack2(A5);
                float a0s = f0.x + f0.y, a1s = f1.x + f1.y, a2s = f2.x + f2.y;
                float a3s = f3.x + f3.y, a4s = f4.x + f4.y, a5s = f5.x + f5.y;

                a0s += __shfl_xor_sync(0xffffffff, a0s, 1);
                a1s += __shfl_xor_sync(0xffffffff, a1s, 1);
                a2s += __shfl_xor_sync(0xffffffff, a2s, 1);
                a3s += __shfl_xor_sync(0xffffffff, a3s, 1);
                a4s += __shfl_xor_sync(0xffffffff, a4s, 1);
                a5s += __shfl_xor_sync(0xffffffff, a5s, 1);
                a0s += __shfl_xor_sync(0xffffffff, a0s, 2);
                a1s += __shfl_xor_sync(0xffffffff, a1s, 2);
                a2s += __shfl_xor_sync(0xffffffff, a2s, 2);
                a3s += __shfl_xor_sync(0xffffffff, a3s, 2);
                a4s += __shfl_xor_sync(0xffffffff, a4s, 2);
                a5s += __shfl_xor_sync(0xffffffff, a5s, 2);

                int x = x0 + xw + mt * 16 + g + 8 * p;
                if (x < W3) {
                    size_t pix = rowbase + x;
                    float rv = (t == 0 ? a2s + hb2 : t == 1 ? a3s + hb3 :
                                t == 2 ? a4s + hb4 : a5s + hb5);
                    out[((size_t)(b * 4 + t)) * plane + pix] = rv;
                    if (t == 0) {
                        float l0 = a0s + hb0, l1 = a1s + hb1;
                        float m = fmaxf(l0, l1);
                        float e0 = __expf(l0 - m), e1 = __expf(l1 - m);
                        float inv = 1.0f / (e0 + e1);
                        out[PROB_OFF + ((size_t)(b * 2 + 0)) * plane + pix] = e0 * inv;
                        out[PROB_OFF + ((size_t)(b * 2 + 1)) * plane + pix] = e1 * inv;
                    }
                }
            }
        }
    }
}

extern "C" void kernel_launch(void* const* d_in, const int* in_sizes, int n_in,
                              void* d_out, int out_size)
{
    const float* x        = (const float*)d_in[0];
    const float* conv1_w  = (const float*)d_in[1];
    const float* conv1_b  = (const float*)d_in[2];
    const float* prelu1_a = (const float*)d_in[3];
    const float* conv2_w  = (const float*)d_in[4];
    const float* conv2_b  = (const float*)d_in[5];
    const float* prelu2_a = (const float*)d_in[6];
    const float* conv3_w  = (const float*)d_in[7];
    const float* conv3_b  = (const float*)d_in[8];
    const float* prelu3_a = (const float*)d_in[9];
    const float* conv41_w = (const float*)d_in[10];
    const float* conv41_b = (const float*)d_in[11];
    const float* conv42_w = (const float*)d_in[12];
    const float* conv42_b = (const float*)d_in[13];
    float* out = (float*)d_out;

    static int attr_done = 0;
    if (!attr_done) {
        cudaFuncSetAttribute(k_conv2_mma, cudaFuncAttributeMaxDynamicSharedMemorySize, SMEM2);
        cudaFuncSetAttribute(k_conv3_heads, cudaFuncAttributeMaxDynamicSharedMemorySize, SMEM3);
        attr_done = 1;
    }

    k_prep<<<10, 256>>>(conv2_w, conv3_w);

    dim3 g1(3, HP, B * 2);
    k_conv1_pool<<<g1, 64>>>(x, conv1_w, conv1_b, prelu1_a);

    dim3 g2(3, (H2 + 7) / 8, B);
    k_conv2_mma<<<g2, 256, SMEM2>>>(conv2_b, prelu2_a);

    dim3 g3(3, (H3 + 7) / 8, B);
    k_conv3_heads<<<g3, 256, SMEM3>>>(conv3_b, prelu3_a,
                                      conv41_w, conv41_b, conv42_w, conv42_b, out);
}

// round 9
// speedup vs baseline: 1.7625x; 1.7625x over previous
#include <cuda_runtime.h>
#include <cstdint>

#define B 16
#define H0 720
#define W0 720
#define HP 359
#define WP 359
#define H2 357
#define W2 357
#define H3 355
#define W3 355

#define W1P 368
#define W2P 368

// A-tile plane stride in float2 units (PL mod 16 == 4 -> conflict-free)
#define PL 1412

__device__ __align__(128) float g_p1[B * 10 * HP * W1P];
__device__ __align__(128) float g_p2[B * 16 * H2 * W2P];

// packed B-fragment images
__device__ __align__(16) float2 g_w2B[18 * 64];
__device__ __align__(16) float2 g_w3B[18 * 128];

typedef unsigned long long ull;

__device__ __forceinline__ ull pack2(float a, float b) {
    ull r;
    asm("mov.b64 %0, {%1,%2};" : "=l"(r) : "f"(a), "f"(b));
    return r;
}
__device__ __forceinline__ void fma2(ull& d, ull a, ull b) {
    asm("fma.rn.f32x2 %0, %1, %2, %0;" : "+l"(d) : "l"(a), "l"(b));
}
__device__ __forceinline__ float2 unpack2(ull v) {
    float2 f;
    asm("mov.b64 {%0,%1}, %2;" : "=f"(f.x), "=f"(f.y) : "l"(v));
    return f;
}
__device__ __forceinline__ float to_tf32(float f) {
    uint32_t u;
    asm("cvt.rna.tf32.f32 %0, %1;" : "=r"(u) : "f"(f));
    return __uint_as_float(u);
}
__device__ __forceinline__ void mma_tf32(float d[4],
                                         float a0, float a1, float a2, float a3,
                                         float b0, float b1) {
    asm("mma.sync.aligned.m16n8k8.row.col.f32.tf32.tf32.f32 "
        "{%0,%1,%2,%3}, {%4,%5,%6,%7}, {%8,%9}, {%0,%1,%2,%3};"
        : "+f"(d[0]), "+f"(d[1]), "+f"(d[2]), "+f"(d[3])
        : "r"(__float_as_uint(a0)), "r"(__float_as_uint(a1)),
          "r"(__float_as_uint(a2)), "r"(__float_as_uint(a3)),
          "r"(__float_as_uint(b0)), "r"(__float_as_uint(b1)));
}

// =====================================================================
// Prep: pack conv2/conv3 weights into packed fragment images
// =====================================================================
__global__ void k_prep(const float* __restrict__ w2, const float* __restrict__ w3)
{
    int e = blockIdx.x * blockDim.x + threadIdx.x;
    if (e < 1152) {
        int nt = e & 1, t = (e >> 1) & 3, g = (e >> 3) & 7, s = e >> 6;
        int h = s & 1, o = s >> 1;
        int ky = o / 3, kx = o - 3 * (o / 3);
        int co = nt * 8 + g;
        int ci0 = h * 8 + t, ci1 = ci0 + 4;
        float f0 = (ci0 < 10) ? w2[((co * 10 + ci0) * 3 + ky) * 3 + kx] : 0.f;
        float f1 = (ci1 < 10) ? w2[((co * 10 + ci1) * 3 + ky) * 3 + kx] : 0.f;
        g_w2B[(s << 6) + (g << 3) + (t << 1) + nt] = make_float2(to_tf32(f0), to_tf32(f1));
    }
    if (e < 2304) {
        int nt = e & 3, t = (e >> 2) & 3, g = (e >> 4) & 7, s = e >> 7;
        int h = s & 1, o = s >> 1;
        int ky = o / 3, kx = o - 3 * (o / 3);
        int co = nt * 8 + g;
        int ci0 = h * 8 + t, ci1 = ci0 + 4;
        float f0 = w3[((co * 16 + ci0) * 3 + ky) * 3 + kx];
        float f1 = w3[((co * 16 + ci1) * 3 + ky) * 3 + kx];
        int idx = (s << 7) + ((nt >> 1) << 6) + (g << 3) + (t << 1) + (nt & 1);
        g_w3B[idx] = make_float2(to_tf32(f0), to_tf32(f1));
    }
}

// =====================================================================
// Kernel 1: conv1(3->10,3x3)+PReLU+maxpool, norm folded (unchanged)
// =====================================================================
__global__ __launch_bounds__(64)
void k_conv1_pool(const float* __restrict__ x,
                  const float* __restrict__ w,
                  const float* __restrict__ bias,
                  const float* __restrict__ alpha)
{
    __shared__ ull   s_wd[135];
    __shared__ float s_b2[5];
    __shared__ float s_a2[5];

    int cg = blockIdx.z & 1;
    int b  = blockIdx.z >> 1;

    for (int i = threadIdx.x; i < 135; i += blockDim.x) {
        float wv = w[cg * 135 + i] * 0.0078125f;
        s_wd[i] = pack2(wv, wv);
    }
    if (threadIdx.x < 5) {
        int co = cg * 5 + threadIdx.x;
        float s = 0.f;
#pragma unroll
        for (int k = 0; k < 27; k++) s += w[co * 27 + k];
        s_b2[threadIdx.x] = bias[co] - 127.5f * 0.0078125f * s;
        s_a2[threadIdx.x] = alpha[co];
    }
    __syncthreads();

    int t = blockIdx.x * blockDim.x + threadIdx.x;
    if (t >= 180) return;
    int py = blockIdx.y;
    int iy = 2 * py;
    int x4 = 4 * t;

    ull acc[5][2][2];
#pragma unroll
    for (int co = 0; co < 5; co++) {
        float bb = s_b2[co];
        ull bp = pack2(bb, bb);
        acc[co][0][0] = bp; acc[co][0][1] = bp;
        acc[co][1][0] = bp; acc[co][1][1] = bp;
    }

#pragma unroll
    for (int ci = 0; ci < 3; ci++) {
        const float* rp = x + ((size_t)(b * 3 + ci) * H0 + iy) * W0 + x4;
        ull pr[4][5];
#pragma unroll
        for (int r = 0; r < 4; r++) {
            float4 v4 = *(const float4*)(rp + (size_t)r * W0);
            float2 v2 = make_float2(0.f, 0.f);
            if (t < 179) v2 = *(const float2*)(rp + (size_t)r * W0 + 4);
            pr[r][0] = pack2(v4.x, v4.y);
            pr[r][1] = pack2(v4.y, v4.z);
            pr[r][2] = pack2(v4.z, v4.w);
            pr[r][3] = pack2(v4.w, v2.x);
            pr[r][4] = pack2(v2.x, v2.y);
        }
#pragma unroll
        for (int co = 0; co < 5; co++) {
#pragma unroll
            for (int ky = 0; ky < 3; ky++)
#pragma unroll
                for (int kx = 0; kx < 3; kx++) {
                    ull wd = s_wd[co * 27 + ci * 9 + ky * 3 + kx];
                    fma2(acc[co][0][0], pr[ky    ][kx], wd);
                    fma2(acc[co][0][1], pr[ky    ][kx + 2], wd);
                    fma2(acc[co][1][0], pr[ky + 1][kx], wd);
                    fma2(acc[co][1][1], pr[ky + 1][kx + 2], wd);
                }
        }
    }

#pragma unroll
    for (int co = 0; co < 5; co++) {
        float a = s_a2[co];
        float2 r00 = unpack2(acc[co][0][0]);
        float2 r01 = unpack2(acc[co][0][1]);
        float2 r10 = unpack2(acc[co][1][0]);
        float2 r11 = unpack2(acc[co][1][1]);
        float p00 = r00.x >= 0.f ? r00.x : a * r00.x;
        float p01 = r00.y >= 0.f ? r00.y : a * r00.y;
        float p10 = r10.x >= 0.f ? r10.x : a * r10.x;
        float p11 = r10.y >= 0.f ? r10.y : a * r10.y;
        float q00 = r01.x >= 0.f ? r01.x : a * r01.x;
        float q01 = r01.y >= 0.f ? r01.y : a * r01.y;
        float q10 = r11.x >= 0.f ? r11.x : a * r11.x;
        float q11 = r11.y >= 0.f ? r11.y : a * r11.y;
        float m0 = fmaxf(fmaxf(p00, p01), fmaxf(p10, p11));
        float m1 = fmaxf(fmaxf(q00, q01), fmaxf(q10, q11));
        float* op = g_p1 + ((size_t)(b * 10 + cg * 5 + co) * HP + py) * W1P + 2 * t;
        *(float2*)op = make_float2(to_tf32(m0), to_tf32(m1));
    }
}

// =====================================================================
// Kernel 2: conv2 via tf32 mma, paired-A layout, 256 thr, forced 2 CTA/SM
// =====================================================================
#define SMEM2 (8 * PL * 8 + 1152 * 8 + 128)
__global__ __launch_bounds__(256, 2)
void k_conv2_mma(const float* __restrict__ bias,
                 const float* __restrict__ alpha)
{
    extern __shared__ char smem[];
    float2* s_in   = (float2*)smem;                        // [8][PL]
    float2* s_B    = (float2*)(smem + 8 * PL * 8);         // 1152
    float*  s_bias = (float*)(smem + 8 * PL * 8 + 1152 * 8);
    float*  s_alpha = s_bias + 16;

    int tid = threadIdx.x;
    int b   = blockIdx.z;
    int y0  = blockIdx.y * 8;
    int x0  = blockIdx.x * 128;

    {
        const float4* src = (const float4*)g_w2B;
        float4* dst = (float4*)s_B;
        for (int i = tid; i < 576; i += 256) dst[i] = src[i];
    }
    if (tid < 16) { s_bias[tid] = bias[tid]; s_alpha[tid] = alpha[tid]; }

    for (int i = tid; i < 8 * 10 * 35; i += 256) {
        int p   = i / 350;
        int rem = i - p * 350;
        int r   = rem / 35;
        int xq  = rem - r * 35;
        int gx  = x0 + xq * 4;
        int grow = y0 + r; if (grow > HP - 1) grow = HP - 1;
        int ci0 = (p >> 2) * 8 + (p & 3);
        int ci1 = ci0 + 4;
        float4 va = make_float4(0.f, 0.f, 0.f, 0.f);
        float4 vb = va;
        if (gx < W1P) {
            if (ci0 < 10) va = *(const float4*)&g_p1[((size_t)(b * 10 + ci0) * HP + grow) * W1P + gx];
            if (ci1 < 10) vb = *(const float4*)&g_p1[((size_t)(b * 10 + ci1) * HP + grow) * W1P + gx];
        }
        float4* dp = (float4*)&s_in[p * PL + r * 140 + xq * 4];
        dp[0] = make_float4(va.x, vb.x, va.y, vb.y);
        dp[1] = make_float4(va.z, vb.z, va.w, vb.w);
    }
    __syncthreads();

    int warp = tid >> 5, lane = tid & 31;
    int warpx = warp & 3, warpr = warp >> 2;
    int g = lane >> 2, t = lane & 3;
    int xw = warpx * 32;
    int rbase = warpr * 4;

    float bval[2][2], aval[2][2];
#pragma unroll
    for (int nt = 0; nt < 2; nt++)
#pragma unroll
        for (int c = 0; c < 2; c++) {
            int co = nt * 8 + 2 * t + c;
            bval[nt][c] = s_bias[co];
            aval[nt][c] = s_alpha[co];
        }

    for (int rr = 0; rr < 4; rr++) {
        int r = rbase + rr;
        int y = y0 + r;
        if (y >= H2) break;
        float D[2][2][4] = {};
#pragma unroll
        for (int s = 0; s < 18; s++) {
            int h = s & 1, o = s >> 1;
            int ky = o / 3, kx = o - 3 * (o / 3);
            float4 b01 = *(const float4*)&s_B[(s << 6) + (g << 3) + (t << 1)];
#pragma unroll
            for (int mt = 0; mt < 2; mt++) {
                const float2* ap = &s_in[(h * 4 + t) * PL + (r + ky) * 140 + xw + mt * 16 + kx + g];
                float2 lo = ap[0];
                float2 hi = ap[8];
                mma_tf32(D[mt][0], lo.x, hi.x, lo.y, hi.y, b01.x, b01.y);
                mma_tf32(D[mt][1], lo.x, hi.x, lo.y, hi.y, b01.z, b01.w);
            }
        }
#pragma unroll
        for (int mt = 0; mt < 2; mt++) {
            int xlo = x0 + xw + mt * 16 + g;
#pragma unroll
            for (int nt = 0; nt < 2; nt++) {
#pragma unroll
                for (int c = 0; c < 2; c++) {
                    int co = nt * 8 + 2 * t + c;
                    float* op = &g_p2[((size_t)(b * 16 + co) * H2 + y) * W2P];
                    float v0 = D[mt][nt][c]     + bval[nt][c];
                    float v1 = D[mt][nt][c + 2] + bval[nt][c];
                    v0 = v0 >= 0.f ? v0 : aval[nt][c] * v0;
                    v1 = v1 >= 0.f ? v1 : aval[nt][c] * v1;
                    if (xlo < W2)     op[xlo]     = to_tf32(v0);
                    if (xlo + 8 < W2) op[xlo + 8] = to_tf32(v1);
                }
            }
        }
    }
}

// =====================================================================
// Kernel 3: conv3+heads via tf32 mma, paired-A, 256 thr, forced 2 CTA/SM
// =====================================================================
#define SMEM3 (8 * PL * 8 + 2304 * 8 + 256)
__global__ __launch_bounds__(256, 2)
void k_conv3_heads(const float* __restrict__ bias,
                   const float* __restrict__ alpha,
                   const float* __restrict__ w41,
                   const float* __restrict__ b41,
                   const float* __restrict__ w42,
                   const float* __restrict__ b42,
                   float* __restrict__ out)
{
    extern __shared__ char smem[];
    float2* s_in   = (float2*)smem;                        // [8][PL]
    float2* s_B    = (float2*)(smem + 8 * PL * 8);         // 2304
    float*  s_bias = (float*)(smem + 8 * PL * 8 + 2304 * 8);
    float*  s_alpha = s_bias + 32;

    int tid = threadIdx.x;
    int b   = blockIdx.z;
    int y0  = blockIdx.y * 8;
    int x0  = blockIdx.x * 128;

    {
        const float4* src = (const float4*)g_w3B;
        float4* dst = (float4*)s_B;
        for (int i = tid; i < 1152; i += 256) dst[i] = src[i];
    }
    if (tid < 32) { s_bias[tid] = bias[tid]; s_alpha[tid] = alpha[tid]; }

    for (int i = tid; i < 8 * 10 * 35; i += 256) {
        int p   = i / 350;
        int rem = i - p * 350;
        int r   = rem / 35;
        int xq  = rem - r * 35;
        int gx  = x0 + xq * 4;
        int grow = y0 + r; if (grow > H2 - 1) grow = H2 - 1;
        int ci0 = (p >> 2) * 8 + (p & 3);
        int ci1 = ci0 + 4;
        float4 va = make_float4(0.f, 0.f, 0.f, 0.f);
        float4 vb = va;
        if (gx < W2P) {
            va = *(const float4*)&g_p2[((size_t)(b * 16 + ci0) * H2 + grow) * W2P + gx];
            vb = *(const float4*)&g_p2[((size_t)(b * 16 + ci1) * H2 + grow) * W2P + gx];
        }
        float4* dp = (float4*)&s_in[p * PL + r * 140 + xq * 4];
        dp[0] = make_float4(va.x, vb.x, va.y, vb.y);
        dp[1] = make_float4(va.z, vb.z, va.w, vb.w);
    }
    __syncthreads();

    int warp = tid >> 5, lane = tid & 31;
    int warpx = warp & 3, warpr = warp >> 2;
    int g = lane >> 2, t = lane & 3;
    int xw = warpx * 32;
    int rbase = warpr * 4;

    float bval[4][2], aval[4][2];
    ull whp[4][6];
#pragma unroll
    for (int nt = 0; nt < 4; nt++) {
        int co0 = nt * 8 + 2 * t, co1 = co0 + 1;
        bval[nt][0] = s_bias[co0];  bval[nt][1] = s_bias[co1];
        aval[nt][0] = s_alpha[co0]; aval[nt][1] = s_alpha[co1];
        whp[nt][0] = pack2(w41[co0],      w41[co1]);
        whp[nt][1] = pack2(w41[32 + co0], w41[32 + co1]);
        whp[nt][2] = pack2(w42[co0],      w42[co1]);
        whp[nt][3] = pack2(w42[32 + co0], w42[32 + co1]);
        whp[nt][4] = pack2(w42[64 + co0], w42[64 + co1]);
        whp[nt][5] = pack2(w42[96 + co0], w42[96 + co1]);
    }
    float hb0 = b41[0], hb1 = b41[1];
    float hb2 = b42[0], hb3 = b42[1], hb4 = b42[2], hb5 = b42[3];

    const size_t plane = (size_t)H3 * W3;
    const size_t PROB_OFF = (size_t)B * 4 * plane;

    for (int rr = 0; rr < 4; rr++) {
        int r = rbase + rr;
        int y = y0 + r;
        if (y >= H3) break;
        float D[2][4][4] = {};
#pragma unroll
        for (int s = 0; s < 18; s++) {
            int h = s & 1, o = s >> 1;
            int ky = o / 3, kx = o - 3 * (o / 3);
            const float2* bp = &s_B[(s << 7) + (g << 3) + (t << 1)];
#pragma unroll
            for (int mt = 0; mt < 2; mt++) {
                const float2* ap = &s_in[(h * 4 + t) * PL + (r + ky) * 140 + xw + mt * 16 + kx + g];
                float2 lo = ap[0];
                float2 hi = ap[8];
                float4 b01 = *(const float4*)bp;
                mma_tf32(D[mt][0], lo.x, hi.x, lo.y, hi.y, b01.x, b01.y);
                mma_tf32(D[mt][1], lo.x, hi.x, lo.y, hi.y, b01.z, b01.w);
                float4 b23 = *(const float4*)(bp + 64);
                mma_tf32(D[mt][2], lo.x, hi.x, lo.y, hi.y, b23.x, b23.y);
                mma_tf32(D[mt][3], lo.x, hi.x, lo.y, hi.y, b23.z, b23.w);
            }
        }

        size_t rowbase = (size_t)y * W3;
#pragma unroll
        for (int mt = 0; mt < 2; mt++) {
#pragma unroll
            for (int p = 0; p < 2; p++) {
                ull A0 = 0, A1 = 0, A2 = 0, A3 = 0, A4 = 0, A5 = 0;
#pragma unroll
                for (int nt = 0; nt < 4; nt++) {
                    float v0 = D[mt][nt][2 * p]     + bval[nt][0];
                    float v1 = D[mt][nt][2 * p + 1] + bval[nt][1];
                    v0 = v0 >= 0.f ? v0 : aval[nt][0] * v0;
                    v1 = v1 >= 0.f ? v1 : aval[nt][1] * v1;
                    ull vp = pack2(v0, v1);
                    fma2(A0, vp, whp[nt][0]);
                    fma2(A1, vp, whp[nt][1]);
                    fma2(A2, vp, whp[nt][2]);
                    fma2(A3, vp, whp[nt][3]);
                    fma2(A4, vp, whp[nt][4]);
                    fma2(A5, vp, whp[nt][5]);
                }
                float2 f0 = unpack2(A0), f1 = unpack2(A1), f2 = unpack2(A2);
                float2 f3 = unpack2(A3), f4 = unpack2(A4), f5 = unpack2(A5);
                float a0s = f0.x + f0.y, a1s = f1.x + f1.y, a2s = f2.x + f2.y;
                float a3s = f3.x + f3.y, a4s = f4.x + f4.y, a5s = f5.x + f5.y;

                a0s += __shfl_xor_sync(0xffffffff, a0s, 1);
                a1s += __shfl_xor_sync(0xffffffff, a1s, 1);
                a2s += __shfl_xor_sync(0xffffffff, a2s, 1);
                a3s += __shfl_xor_sync(0xffffffff, a3s, 1);
                a4s += __shfl_xor_sync(0xffffffff, a4s, 1);
                a5s += __shfl_xor_sync(0xffffffff, a5s, 1);
                a0s += __shfl_xor_sync(0xffffffff, a0s, 2);
                a1s += __shfl_xor_sync(0xffffffff, a1s, 2);
                a2s += __shfl_xor_sync(0xffffffff, a2s, 2);
                a3s += __shfl_xor_sync(0xffffffff, a3s, 2);
                a4s += __shfl_xor_sync(0xffffffff, a4s, 2);
                a5s += __shfl_xor_sync(0xffffffff, a5s, 2);

                int x = x0 + xw + mt * 16 + g + 8 * p;
                if (x < W3) {
                    size_t pix = rowbase + x;
                    float rv = (t == 0 ? a2s + hb2 : t == 1 ? a3s + hb3 :
                                t == 2 ? a4s + hb4 : a5s + hb5);
                    out[((size_t)(b * 4 + t)) * plane + pix] = rv;
                    if (t == 0) {
                        float l0 = a0s + hb0, l1 = a1s + hb1;
                        float m = fmaxf(l0, l1);
                        float e0 = __expf(l0 - m), e1 = __expf(l1 - m);
                        float inv = 1.0f / (e0 + e1);
                        out[PROB_OFF + ((size_t)(b * 2 + 0)) * plane + pix] = e0 * inv;
                        out[PROB_OFF + ((size_t)(b * 2 + 1)) * plane + pix] = e1 * inv;
                    }
                }
            }
        }
    }
}

extern "C" void kernel_launch(void* const* d_in, const int* in_sizes, int n_in,
                              void* d_out, int out_size)
{
    const float* x        = (const float*)d_in[0];
    const float* conv1_w  = (const float*)d_in[1];
    const float* conv1_b  = (const float*)d_in[2];
    const float* prelu1_a = (const float*)d_in[3];
    const float* conv2_w  = (const float*)d_in[4];
    const float* conv2_b  = (const float*)d_in[5];
    const float* prelu2_a = (const float*)d_in[6];
    const float* conv3_w  = (const float*)d_in[7];
    const float* conv3_b  = (const float*)d_in[8];
    const float* prelu3_a = (const float*)d_in[9];
    const float* conv41_w = (const float*)d_in[10];
    const float* conv41_b = (const float*)d_in[11];
    const float* conv42_w = (const float*)d_in[12];
    const float* conv42_b = (const float*)d_in[13];
    float* out = (float*)d_out;

    static int attr_done = 0;
    if (!attr_done) {
        cudaFuncSetAttribute(k_conv2_mma, cudaFuncAttributeMaxDynamicSharedMemorySize, SMEM2);
        cudaFuncSetAttribute(k_conv3_heads, cudaFuncAttributeMaxDynamicSharedMemorySize, SMEM3);
        attr_done = 1;
    }

    k_prep<<<10, 256>>>(conv2_w, conv3_w);

    dim3 g1(3, HP, B * 2);
    k_conv1_pool<<<g1, 64>>>(x, conv1_w, conv1_b, prelu1_a);

    dim3 g2(3, (H2 + 7) / 8, B);
    k_conv2_mma<<<g2, 256, SMEM2>>>(conv2_b, prelu2_a);

    dim3 g3(3, (H3 + 7) / 8, B);
    k_conv3_heads<<<g3, 256, SMEM3>>>(conv3_b, prelu3_a,
                                      conv41_w, conv41_b, conv42_w, conv42_b, out);
}